// round 1
// baseline (speedup 1.0000x reference)
#include <cuda_runtime.h>

// CRPS loss:
//   samples: [16, 4, 1, 256, 256] fp32  (d_in[0], 4194304 elems)
//   target:  [4, 1, 256, 256]     fp32  (d_in[1], 262144 elems)
//   out: scalar fp32 = mean_p( mean_i|s_i - y| - sum_{i<j}|s_i - s_j|/N^2 )
//
// Strategy: one thread per float4 pixel-group. 16 strided float4 loads
// (coalesced across threads, 16-deep MLP). 120 unique pairs computed
// directly. Block reduction -> one double atomicAdd per block.

#define NS   16
#define P    262144        // pixels
#define P4   (P / 4)       // float4 groups = 65536
#define NTHREADS 256
#define NBLOCKS  (P4 / NTHREADS)   // 256

__device__ double g_acc;

__global__ void k_zero() { g_acc = 0.0; }

__global__ void __launch_bounds__(NTHREADS)
k_crps(const float4* __restrict__ s, const float4* __restrict__ y) {
    const int p = blockIdx.x * NTHREADS + threadIdx.x;

    // Load all 16 samples for this float4 pixel group (stride P4 float4s).
    float4 v[NS];
#pragma unroll
    for (int i = 0; i < NS; i++) {
        v[i] = s[(size_t)i * P4 + p];
    }
    const float4 t = y[p];

    // term1: sum_i |s_i - y|
    float a1x = 0.f, a1y = 0.f, a1z = 0.f, a1w = 0.f;
#pragma unroll
    for (int i = 0; i < NS; i++) {
        a1x += fabsf(v[i].x - t.x);
        a1y += fabsf(v[i].y - t.y);
        a1z += fabsf(v[i].z - t.z);
        a1w += fabsf(v[i].w - t.w);
    }

    // term2 raw: sum over unique pairs |s_i - s_j|
    float a2x = 0.f, a2y = 0.f, a2z = 0.f, a2w = 0.f;
#pragma unroll
    for (int i = 0; i < NS; i++) {
#pragma unroll
        for (int j = i + 1; j < NS; j++) {
            a2x += fabsf(v[i].x - v[j].x);
            a2y += fabsf(v[i].y - v[j].y);
            a2z += fabsf(v[i].z - v[j].z);
            a2w += fabsf(v[i].w - v[j].w);
        }
    }

    // crps contribution of the 4 pixels:
    //   term1_sum/16 - pair_sum/256  (per pixel), summed over 4 pixels
    float val = (a1x + a1y + a1z + a1w) * (1.0f / 16.0f)
              - (a2x + a2y + a2z + a2w) * (1.0f / 256.0f);

    // Warp reduce
#pragma unroll
    for (int o = 16; o > 0; o >>= 1)
        val += __shfl_xor_sync(0xFFFFFFFFu, val, o);

    __shared__ float sm[NTHREADS / 32];
    const int lane = threadIdx.x & 31;
    const int wid  = threadIdx.x >> 5;
    if (lane == 0) sm[wid] = val;
    __syncthreads();

    if (threadIdx.x < (NTHREADS / 32)) {
        float w = sm[threadIdx.x];
#pragma unroll
        for (int o = (NTHREADS / 64); o > 0; o >>= 1)
            w += __shfl_xor_sync(0xFFu, w, o);
        if (threadIdx.x == 0)
            atomicAdd(&g_acc, (double)w);
    }
}

__global__ void k_fin(float* out) {
    *out = (float)(g_acc * (1.0 / (double)P));
}

extern "C" void kernel_launch(void* const* d_in, const int* in_sizes, int n_in,
                              void* d_out, int out_size) {
    const float4* samples = (const float4*)d_in[0];
    const float4* target  = (const float4*)d_in[1];
    float* out = (float*)d_out;

    k_zero<<<1, 1>>>();
    k_crps<<<NBLOCKS, NTHREADS>>>(samples, target);
    k_fin<<<1, 1>>>(out);
}